// round 7
// baseline (speedup 1.0000x reference)
#include <cuda_runtime.h>
#include <cstdint>

// Problem constants (fixed by the reference)
#define BATCH 4
#define DIM   192
#define RED   48          // DIM / 4
#define H     256
#define W     256
#define KK    9           // 3x3
#define EPS   1e-5f
#define NCH   (BATCH * DIM)   // 768 channel-slices
#define HW    (H * W)         // 65536 pixels per slice

// Scratch (allocation-free rule: __device__ globals)
__device__ float  g_pooled[NCH];      // per (b,c) mean
__device__ float4 g_wt4[NCH];         // masked taps: (w00, w01, w02, w10)

// ---------------------------------------------------------------------------
// Kernel 1: global average pool. One block per (b,c) slice; 256 threads
// each accumulate 64 float4's, then tree-reduce in shared.
// (measured 6.26 TB/s — at the read ceiling; unchanged)
// ---------------------------------------------------------------------------
__global__ void __launch_bounds__(256) pool_kernel(const float* __restrict__ x) {
    const int bc  = blockIdx.x;               // 0..767
    const int tid = threadIdx.x;
    const float4* xin = reinterpret_cast<const float4*>(x + (size_t)bc * HW);

    float acc = 0.f;
    #pragma unroll 8
    for (int i = tid; i < HW / 4; i += 256) {
        float4 v = __ldg(xin + i);
        acc += (v.x + v.y) + (v.z + v.w);
    }
    __shared__ float sred[256];
    sred[tid] = acc;
    __syncthreads();
    #pragma unroll
    for (int s = 128; s >= 32; s >>= 1) {
        if (tid < s) sred[tid] += sred[tid + s];
        __syncthreads();
    }
    if (tid < 32) {
        float v = sred[tid];
        #pragma unroll
        for (int off = 16; off; off >>= 1)
            v += __shfl_down_sync(0xffffffffu, v, off);
        if (tid == 0) g_pooled[bc] = v * (1.f / (float)HW);
    }
}

// ---------------------------------------------------------------------------
// Kernel 2: dynamic weight generation (tiny; one block per batch sample).
// ---------------------------------------------------------------------------
__global__ void __launch_bounds__(192) weights_kernel(
    const float* __restrict__ w1,            // [48,192]
    const float* __restrict__ gamma,
    const float* __restrict__ beta,
    const float* __restrict__ rmean,
    const float* __restrict__ rvar,
    const float* __restrict__ w2,            // [1728,48]
    const float* __restrict__ b2)            // [1728]
{
    const int b   = blockIdx.x;   // 0..3
    const int tid = threadIdx.x;  // 0..191

    __shared__ float sp[DIM];     // pooled[b,:]
    __shared__ float st[RED];     // t[b,:]

    sp[tid] = g_pooled[b * DIM + tid];
    __syncthreads();

    if (tid < RED) {
        const float* w1r = w1 + tid * DIM;
        float acc = 0.f;
        #pragma unroll 4
        for (int k = 0; k < DIM; k++) acc += sp[k] * __ldg(w1r + k);
        float v = __ldg(gamma + tid) * (acc - __ldg(rmean + tid))
                  * rsqrtf(__ldg(rvar + tid) + EPS) + __ldg(beta + tid);
        st[tid] = fmaxf(v, 0.f);
    }
    __syncthreads();

    // Each thread = one channel c; taps k=0..3 are the only unmasked ones
    const int c = tid;
    float tap[4];
    #pragma unroll
    for (int k = 0; k < 4; k++) {
        const int row = c * KK + k;
        const float* w2r = w2 + row * RED;
        float acc = __ldg(b2 + row);
        #pragma unroll
        for (int j = 0; j < RED; j++) acc += st[j] * __ldg(w2r + j);
        tap[k] = acc;
    }
    g_wt4[b * DIM + c] = make_float4(tap[0], tap[1], tap[2], tap[3]);
}

// ---------------------------------------------------------------------------
// Kernel 3 v2: masked depthwise conv (4 active taps) + bias.
//   out[y][x] = w00*in[y-1][x-1] + w01*in[y-1][x] + w02*in[y-1][x+1]
//             + w10*in[y][x-1] + bias[c]
// Register tile: each thread produces 2 rows x 8 cols.
// Loads 3 input rows once; row y reused as both "up" and "center".
// Warp = 32 threads x 8 cols = full 256-col row -> fully coalesced.
// Block 256 thr = 8 row-pairs -> covers 16 rows; 16 blocks per channel.
// ---------------------------------------------------------------------------
__device__ __forceinline__ void load_row10(const float* __restrict__ row,
                                           int x0, float* __restrict__ buf) {
    // buf[0..9] = cols x0-1 .. x0+8 (zero-padded at image edges)
    float4 a = *reinterpret_cast<const float4*>(row + x0);
    float4 b = *reinterpret_cast<const float4*>(row + x0 + 4);
    buf[1] = a.x; buf[2] = a.y; buf[3] = a.z; buf[4] = a.w;
    buf[5] = b.x; buf[6] = b.y; buf[7] = b.z; buf[8] = b.w;
    buf[0] = (x0 > 0)     ? row[x0 - 1] : 0.f;
    buf[9] = (x0 + 8 < W) ? row[x0 + 8] : 0.f;
}

__global__ void __launch_bounds__(256) conv_kernel(
    const float* __restrict__ x,
    const float* __restrict__ bias,
    float* __restrict__ out)
{
    const int bc = blockIdx.y;                      // 0..767
    const int c  = bc - (bc / DIM) * DIM;           // bc % DIM
    const float* __restrict__ xin = x   + (size_t)bc * HW;
    float*       __restrict__ o   = out + (size_t)bc * HW;

    const float4 wv = g_wt4[bc];                    // taps (w00,w01,w02,w10)
    const float  bv = __ldg(bias + c);

    const int tid = threadIdx.x;
    const int tx  = tid & 31;                       // 0..31
    const int ty  = tid >> 5;                       // 0..7
    const int x0  = tx << 3;                        // col base (mult of 8)
    const int y0  = (blockIdx.x << 4) + (ty << 1);  // first of 2 output rows

    float rm1[10], r0[10], r1[10];                  // rows y0-1, y0, y0+1
    if (y0 > 0) {
        load_row10(xin + (y0 - 1) * W, x0, rm1);
    } else {
        #pragma unroll
        for (int i = 0; i < 10; i++) rm1[i] = 0.f;
    }
    load_row10(xin + y0 * W,       x0, r0);
    load_row10(xin + (y0 + 1) * W, x0, r1);

    float o0[8], o1[8];
    #pragma unroll
    for (int j = 0; j < 8; j++) {
        // out row y0: up = rm1, center = r0
        o0[j] = fmaf(wv.x, rm1[j],
                fmaf(wv.y, rm1[j + 1],
                fmaf(wv.z, rm1[j + 2],
                fmaf(wv.w, r0[j], bv))));
        // out row y0+1: up = r0, center = r1
        o1[j] = fmaf(wv.x, r0[j],
                fmaf(wv.y, r0[j + 1],
                fmaf(wv.z, r0[j + 2],
                fmaf(wv.w, r1[j], bv))));
    }

    float* po0 = o + y0 * W + x0;
    float* po1 = po0 + W;
    *reinterpret_cast<float4*>(po0)     = make_float4(o0[0], o0[1], o0[2], o0[3]);
    *reinterpret_cast<float4*>(po0 + 4) = make_float4(o0[4], o0[5], o0[6], o0[7]);
    *reinterpret_cast<float4*>(po1)     = make_float4(o1[0], o1[1], o1[2], o1[3]);
    *reinterpret_cast<float4*>(po1 + 4) = make_float4(o1[4], o1[5], o1[6], o1[7]);
}

// ---------------------------------------------------------------------------
// Launch. Inputs (metadata order):
// 0:x 1:w1 2:gamma 3:beta 4:running_mean 5:running_var 6:w2 7:b2 8:bias
// ---------------------------------------------------------------------------
extern "C" void kernel_launch(void* const* d_in, const int* in_sizes, int n_in,
                              void* d_out, int out_size) {
    const float* x     = (const float*)d_in[0];
    const float* w1    = (const float*)d_in[1];
    const float* gamma = (const float*)d_in[2];
    const float* beta  = (const float*)d_in[3];
    const float* rmean = (const float*)d_in[4];
    const float* rvar  = (const float*)d_in[5];
    const float* w2    = (const float*)d_in[6];
    const float* b2    = (const float*)d_in[7];
    const float* bias  = (const float*)d_in[8];
    float* out = (float*)d_out;

    pool_kernel<<<NCH, 256>>>(x);
    weights_kernel<<<BATCH, DIM>>>(w1, gamma, beta, rmean, rvar, w2, b2);
    conv_kernel<<<dim3(H / 16, NCH), 256>>>(x, bias, out);
}